// round 1
// baseline (speedup 1.0000x reference)
#include <cuda_runtime.h>

// ---------------- problem constants ----------------
#define NNODE 16000
#define NEDGE 128000
#define GATD 768          // GAT dim
#define XD 800            // meta-in dim (768 gat + 32 node)
#define MD 128            // meta out dim
#define PD 384            // P1(dst part) | P2(src part) | Xself

// ---------------- device scratch (no allocs allowed) ----------------
__device__ float    g_h[NNODE * GATD];       // 49 MB
__device__ float    g_x[NNODE * XD];         // 51 MB  (cols 0:768 gat_out, 768:800 nf)
__device__ float    g_P[NNODE * PD];         // 24.6 MB
__device__ float    g_EW[NEDGE * MD];        // 65.5 MB
__device__ float    g_ea[NEDGE * 16];        // 8.2 MB
__device__ float    g_asrc[NNODE];
__device__ float    g_adst[NNODE];
__device__ unsigned g_amax[NNODE];           // ordered-float bits
__device__ float    g_denom[NNODE];
__device__ float    g_alphaE[NEDGE];
__device__ float    g_exE[NEDGE];
__device__ int      g_deg[NNODE];
__device__ int      g_rowstart[NNODE];
__device__ int      g_pos[NNODE];
__device__ int      g_csr_src[NEDGE];
__device__ int      g_csr_eid[NEDGE];
__device__ float    g_Wcat[XD * PD];         // [800 x 384] = W_dst|W_src|W_self

// ---------------- helpers ----------------
__device__ __forceinline__ float lrelu(float x) { return x >= 0.f ? x : 0.2f * x; }

__device__ __forceinline__ unsigned f2o(float f) {
    unsigned b = __float_as_uint(f);
    return (b & 0x80000000u) ? ~b : (b | 0x80000000u);
}
__device__ __forceinline__ float o2f(unsigned b) {
    b = (b & 0x80000000u) ? (b & 0x7fffffffu) : ~b;
    return __uint_as_float(b);
}

// ---------------- tiny learners ----------------
__global__ void k_nodeL(const float* __restrict__ nf, const float* __restrict__ W,
                        const float* __restrict__ b) {
    int idx = blockIdx.x * blockDim.x + threadIdx.x;
    if (idx >= NNODE * 32) return;
    int i = idx >> 5, j = idx & 31;
    const float* r = nf + i * 32;
    float s = b[j];
#pragma unroll
    for (int k = 0; k < 32; k++) s += r[k] * W[k * 32 + j];
    g_x[i * XD + GATD + j] = s;
}

__global__ void k_edgeL(const float* __restrict__ ea, const float* __restrict__ W,
                        const float* __restrict__ b) {
    int idx = blockIdx.x * blockDim.x + threadIdx.x;
    if (idx >= NEDGE * 16) return;
    int e = idx >> 4, j = idx & 15;
    const float* r = ea + e * 16;
    float s = b[j];
#pragma unroll
    for (int k = 0; k < 16; k++) s += r[k] * W[k * 16 + j];
    g_ea[e * 16 + j] = s;
}

// ---------------- generic fp32 SGEMM: 128x128 tile, BK=8, 8x8/thread ----------------
template <int Ncols, int Kdim>
__device__ __forceinline__ void sgemm_body(const float* __restrict__ A,
                                           const float* __restrict__ B,
                                           float* __restrict__ C) {
    __shared__ float As[8][128];
    __shared__ float Bs[8][128];
    int tid = threadIdx.x;
    int bm = blockIdx.y * 128;
    int bn = blockIdx.x * 128;

    int arow = tid >> 1;            // 0..127
    int acol = (tid & 1) * 4;       // 0 or 4
    int brow = tid >> 5;            // 0..7
    int bcol = (tid & 31) * 4;      // 0..124

    int trow = (tid >> 4) * 8;      // 0..120
    int tcol = (tid & 15) * 8;      // 0..120

    float acc[8][8];
#pragma unroll
    for (int i = 0; i < 8; i++)
#pragma unroll
        for (int j = 0; j < 8; j++) acc[i][j] = 0.f;

    for (int k0 = 0; k0 < Kdim; k0 += 8) {
        float4 av = *(const float4*)&A[(size_t)(bm + arow) * Kdim + k0 + acol];
        As[acol + 0][arow] = av.x;
        As[acol + 1][arow] = av.y;
        As[acol + 2][arow] = av.z;
        As[acol + 3][arow] = av.w;
        float4 bv = *(const float4*)&B[(size_t)(k0 + brow) * Ncols + bn + bcol];
        *(float4*)&Bs[brow][bcol] = bv;
        __syncthreads();
#pragma unroll
        for (int k = 0; k < 8; k++) {
            float ar[8], br[8];
            *(float4*)&ar[0] = *(const float4*)&As[k][trow];
            *(float4*)&ar[4] = *(const float4*)&As[k][trow + 4];
            *(float4*)&br[0] = *(const float4*)&Bs[k][tcol];
            *(float4*)&br[4] = *(const float4*)&Bs[k][tcol + 4];
#pragma unroll
            for (int i = 0; i < 8; i++)
#pragma unroll
                for (int j = 0; j < 8; j++) acc[i][j] += ar[i] * br[j];
        }
        __syncthreads();
    }
#pragma unroll
    for (int i = 0; i < 8; i++)
#pragma unroll
        for (int j = 0; j < 8; j += 4) {
            float4 v = make_float4(acc[i][j], acc[i][j + 1], acc[i][j + 2], acc[i][j + 3]);
            *(float4*)&C[(size_t)(bm + trow + i) * Ncols + bn + tcol + j] = v;
        }
}

__global__ void __launch_bounds__(256) k_sgemm_h(const float* __restrict__ A,
                                                 const float* __restrict__ B) {
    sgemm_body<GATD, GATD>(A, B, g_h);   // h = mf @ W_gat   (16000x768, K=768)
}
__global__ void __launch_bounds__(256) k_sgemm_p() {
    sgemm_body<PD, XD>(g_x, g_Wcat, g_P); // P = x @ Wcat    (16000x384, K=800)
}

// ---------------- attention scalars ----------------
__global__ void k_att(const float* __restrict__ att_src, const float* __restrict__ att_dst) {
    int warp = (blockIdx.x * blockDim.x + threadIdx.x) >> 5;
    int lane = threadIdx.x & 31;
    if (warp >= NNODE) return;
    const float* hr = g_h + (size_t)warp * GATD;
    float s1 = 0.f, s2 = 0.f;
    for (int j = lane; j < GATD; j += 32) {
        float v = hr[j];
        s1 += v * att_src[j];
        s2 += v * att_dst[j];
    }
#pragma unroll
    for (int off = 16; off > 0; off >>= 1) {
        s1 += __shfl_down_sync(0xffffffffu, s1, off);
        s2 += __shfl_down_sync(0xffffffffu, s2, off);
    }
    if (lane == 0) { g_asrc[warp] = s1; g_adst[warp] = s2; }
}

__global__ void k_init_node() {
    int i = blockIdx.x * blockDim.x + threadIdx.x;
    if (i >= NNODE) return;
    float al = lrelu(g_asrc[i] + g_adst[i]);   // self-loop alpha
    g_amax[i] = f2o(al);
    g_deg[i] = 0;
}

__global__ void k_edge_alpha(const int* __restrict__ ei) {
    int e = blockIdx.x * blockDim.x + threadIdx.x;
    if (e >= NEDGE) return;
    int s = ei[e], d = ei[NEDGE + e];
    float al = lrelu(g_asrc[s] + g_adst[d]);
    g_alphaE[e] = al;
    atomicMax(&g_amax[d], f2o(al));
    atomicAdd(&g_deg[d], 1);
}

// exclusive scan of deg -> rowstart (and pos copy); one block
__global__ void k_scan() {
    __shared__ int sh[1024];
    __shared__ int s_carry;
    int tid = threadIdx.x;
    if (tid == 0) s_carry = 0;
    __syncthreads();
    for (int base = 0; base < NNODE; base += 1024) {
        int i = base + tid;
        int v = (i < NNODE) ? g_deg[i] : 0;
        sh[tid] = v;
        __syncthreads();
        for (int off = 1; off < 1024; off <<= 1) {
            int t = (tid >= off) ? sh[tid - off] : 0;
            __syncthreads();
            sh[tid] += t;
            __syncthreads();
        }
        int incl = sh[tid];
        int carry = s_carry;
        if (i < NNODE) {
            int excl = carry + incl - v;
            g_rowstart[i] = excl;
            g_pos[i] = excl;
        }
        __syncthreads();
        if (tid == 1023) s_carry = carry + incl;
        __syncthreads();
    }
}

__global__ void k_csr_fill(const int* __restrict__ ei) {
    int e = blockIdx.x * blockDim.x + threadIdx.x;
    if (e >= NEDGE) return;
    int s = ei[e], d = ei[NEDGE + e];
    int p = atomicAdd(&g_pos[d], 1);
    g_csr_src[p] = s;
    g_csr_eid[p] = e;
}

__global__ void k_denom_init() {
    int i = blockIdx.x * blockDim.x + threadIdx.x;
    if (i >= NNODE) return;
    float al = lrelu(g_asrc[i] + g_adst[i]);
    g_denom[i] = expf(al - o2f(g_amax[i]));
}

__global__ void k_edge_exp() {
    int e = blockIdx.x * blockDim.x + threadIdx.x;
    if (e >= NEDGE) return;
    // dst recovered through csr? cheaper: we need dst again -> read from alpha path
    // we stored nothing; use eid->dst via exE pass needing ei. (passed as arg instead)
}

__global__ void k_edge_exp2(const int* __restrict__ ei) {
    int e = blockIdx.x * blockDim.x + threadIdx.x;
    if (e >= NEDGE) return;
    int d = ei[NEDGE + e];
    float ex = expf(g_alphaE[e] - o2f(g_amax[d]));
    g_exE[e] = ex;
    atomicAdd(&g_denom[d], ex);
}

// ---------------- GAT gather-aggregation: warp per node ----------------
__global__ void k_gat_aggr(const float* __restrict__ b_gat) {
    int warp = (blockIdx.x * blockDim.x + threadIdx.x) >> 5;
    int lane = threadIdx.x & 31;
    if (warp >= NNODE) return;
    int i = warp;
    float amaxv = o2f(g_amax[i]);
    float als = lrelu(g_asrc[i] + g_adst[i]);
    float inv_den = 1.0f / g_denom[i];
    float cs = expf(als - amaxv) * inv_den;

    const float4* hrow = (const float4*)(g_h + (size_t)i * GATD);
    const float4* bg = (const float4*)b_gat;
    float4 acc[6];
#pragma unroll
    for (int t = 0; t < 6; t++) {
        float4 hv = hrow[lane + 32 * t];
        float4 bv = bg[lane + 32 * t];
        acc[t].x = cs * hv.x + bv.x;
        acc[t].y = cs * hv.y + bv.y;
        acc[t].z = cs * hv.z + bv.z;
        acc[t].w = cs * hv.w + bv.w;
    }
    int rs = g_rowstart[i], d = g_deg[i];
    for (int k = 0; k < d; k++) {
        int s = g_csr_src[rs + k];
        float coef = g_exE[g_csr_eid[rs + k]] * inv_den;
        const float4* hs = (const float4*)(g_h + (size_t)s * GATD);
#pragma unroll
        for (int t = 0; t < 6; t++) {
            float4 hv = __ldg(&hs[lane + 32 * t]);
            acc[t].x += coef * hv.x;
            acc[t].y += coef * hv.y;
            acc[t].z += coef * hv.z;
            acc[t].w += coef * hv.w;
        }
    }
    float4* xrow = (float4*)(g_x + (size_t)i * XD);
#pragma unroll
    for (int t = 0; t < 6; t++) xrow[lane + 32 * t] = acc[t];
}

// ---------------- build Wcat = [W_nbr[0:800] | W_nbr[800:1600] | W_self] ----------------
__global__ void k_wcat(const float* __restrict__ Wn, const float* __restrict__ Ws) {
    int idx = blockIdx.x * blockDim.x + threadIdx.x;
    if (idx >= XD * PD) return;
    int k = idx / PD, c = idx % PD;
    float v;
    if (c < 128) v = Wn[k * 128 + c];
    else if (c < 256) v = Wn[(800 + k) * 128 + (c - 128)];
    else v = Ws[k * 128 + (c - 256)];
    g_Wcat[idx] = v;
}

// ---------------- EW[e] = ea[e] @ W_nbr[1600:1616]  (2 edges / 256-thr block) ----------------
__global__ void k_ew(const float* __restrict__ W_nbr) {
    __shared__ float We[16 * 128];
    for (int t = threadIdx.x; t < 2048; t += 256) We[t] = W_nbr[1600 * 128 + t];
    __syncthreads();
    int e = blockIdx.x * 2 + (threadIdx.x >> 7);
    int d = threadIdx.x & 127;
    const float* ear = g_ea + e * 16;
    float s = 0.f;
#pragma unroll
    for (int k = 0; k < 16; k++) s += ear[k] * We[k * 128 + d];
    g_EW[e * 128 + d] = s;
}

// ---------------- final aggregation: warp per node, lane = 4 output dims ----------------
__global__ void k_meta(float* __restrict__ out, const float* __restrict__ b_nbr,
                       const float* __restrict__ b_self) {
    int warp = (blockIdx.x * blockDim.x + threadIdx.x) >> 5;
    int lane = threadIdx.x & 31;
    if (warp >= NNODE) return;
    int i = warp;
    const float4* Pr = (const float4*)(g_P + (size_t)i * PD);
    float4 p1 = Pr[lane];        // dst-part
    float4 xs = Pr[64 + lane];   // self-part
    float4 bn = ((const float4*)b_nbr)[lane];
    float4 bs = ((const float4*)b_self)[lane];
    float degf = (float)g_deg[i];
    float4 acc;
    acc.x = xs.x + bs.x + degf * (p1.x + bn.x);
    acc.y = xs.y + bs.y + degf * (p1.y + bn.y);
    acc.z = xs.z + bs.z + degf * (p1.z + bn.z);
    acc.w = xs.w + bs.w + degf * (p1.w + bn.w);
    int rs = g_rowstart[i], d = g_deg[i];
    for (int k = 0; k < d; k++) {
        int s = g_csr_src[rs + k];
        int e = g_csr_eid[rs + k];
        float4 p2 = __ldg(&((const float4*)(g_P + (size_t)s * PD))[32 + lane]);
        float4 ew = __ldg(&((const float4*)(g_EW + (size_t)e * MD))[lane]);
        acc.x += p2.x + ew.x;
        acc.y += p2.y + ew.y;
        acc.z += p2.z + ew.z;
        acc.w += p2.w + ew.w;
    }
    ((float4*)(out + (size_t)i * MD))[lane] = acc;
}

// ---------------- launch ----------------
extern "C" void kernel_launch(void* const* d_in, const int* in_sizes, int n_in,
                              void* d_out, int out_size) {
    const float* node_feature    = (const float*)d_in[0];
    const float* edge_attr       = (const float*)d_in[1];
    const float* message_feature = (const float*)d_in[2];
    const int*   edge_index      = (const int*)d_in[3];
    const float* W_node = (const float*)d_in[4];
    const float* b_node = (const float*)d_in[5];
    const float* W_edge = (const float*)d_in[6];
    const float* b_edge = (const float*)d_in[7];
    const float* W_gat  = (const float*)d_in[8];
    const float* att_src = (const float*)d_in[9];
    const float* att_dst = (const float*)d_in[10];
    const float* b_gat  = (const float*)d_in[11];
    const float* W_nbr  = (const float*)d_in[12];
    const float* b_nbr  = (const float*)d_in[13];
    const float* W_self = (const float*)d_in[14];
    const float* b_self = (const float*)d_in[15];
    float* out = (float*)d_out;

    // learners
    k_nodeL<<<(NNODE * 32 + 255) / 256, 256>>>(node_feature, W_node, b_node);
    k_edgeL<<<(NEDGE * 16 + 255) / 256, 256>>>(edge_attr, W_edge, b_edge);

    // big GEMM: h = mf @ W_gat
    k_sgemm_h<<<dim3(GATD / 128, NNODE / 128), 256>>>(message_feature, W_gat);

    // attention scalars + softmax structure
    k_att<<<(NNODE * 32 + 255) / 256, 256>>>(att_src, att_dst);
    k_init_node<<<(NNODE + 255) / 256, 256>>>();
    k_edge_alpha<<<(NEDGE + 255) / 256, 256>>>(edge_index);
    k_scan<<<1, 1024>>>();
    k_csr_fill<<<(NEDGE + 255) / 256, 256>>>(edge_index);
    k_denom_init<<<(NNODE + 255) / 256, 256>>>();
    k_edge_exp2<<<(NEDGE + 255) / 256, 256>>>(edge_index);

    // GAT aggregation -> x[:, 0:768]
    k_gat_aggr<<<(NNODE * 32 + 255) / 256, 256>>>(b_gat);

    // meta GEMMs
    k_wcat<<<(XD * PD + 255) / 256, 256>>>(W_nbr, W_self);
    k_sgemm_p<<<dim3(PD / 128, NNODE / 128), 256>>>();
    k_ew<<<NEDGE / 2, 256>>>(W_nbr);

    // final per-node aggregation -> out
    k_meta<<<(NNODE * 32 + 255) / 256, 256>>>(out, b_nbr, b_self);
}

// round 3
// speedup vs baseline: 1.5252x; 1.5252x over previous
#include <cuda_runtime.h>
#include <cuda_bf16.h>
#include <cstdint>

// ---------------- problem constants ----------------
#define NNODE 16000
#define NEDGE 128000
#define GATD 768          // GAT dim
#define XD 800            // meta-in dim (768 gat + 32 node)
#define XDP 832           // padded K for GEMM2 (26 x 32)
#define MD 128            // meta out dim
#define PD 384            // P1(dst part) | P2(src part) | Xself

// ---------------- device scratch (no allocs allowed) ----------------
__device__ float    g_h[NNODE * GATD];       // 49 MB
__device__ float    g_x[NNODE * XD];         // 51 MB  (cols 0:768 gat_out, 768:800 nf)
__device__ float    g_P[NNODE * PD];         // 24.6 MB
__device__ float    g_EW[NEDGE * MD];        // 65.5 MB
__device__ float    g_ea[NEDGE * 16];        // 8.2 MB
__device__ float    g_asrc[NNODE];
__device__ float    g_adst[NNODE];
__device__ unsigned g_amax[NNODE];           // ordered-float bits
__device__ float    g_denom[NNODE];
__device__ float    g_alphaE[NEDGE];
__device__ float    g_exE[NEDGE];
__device__ int      g_deg[NNODE];
__device__ int      g_rowstart[NNODE];
__device__ int      g_pos[NNODE];
__device__ int      g_csr_src[NEDGE];
__device__ int      g_csr_eid[NEDGE];
// bf16 split operands for tensor-core GEMMs
__device__ __nv_bfloat16 g_A1h[NNODE * GATD];
__device__ __nv_bfloat16 g_A1l[NNODE * GATD];
__device__ __nv_bfloat16 g_Xh[NNODE * XDP];
__device__ __nv_bfloat16 g_Xl[NNODE * XDP];
__device__ __nv_bfloat16 g_W1h[GATD * GATD];   // W_gat^T  [n,k]
__device__ __nv_bfloat16 g_W1l[GATD * GATD];
__device__ __nv_bfloat16 g_W2h[PD * XDP];      // Wcat^T   [n,k]
__device__ __nv_bfloat16 g_W2l[PD * XDP];

// ---------------- helpers ----------------
__device__ __forceinline__ float lrelu(float x) { return x >= 0.f ? x : 0.2f * x; }
__device__ __forceinline__ unsigned f2o(float f) {
    unsigned b = __float_as_uint(f);
    return (b & 0x80000000u) ? ~b : (b | 0x80000000u);
}
__device__ __forceinline__ float o2f(unsigned b) {
    b = (b & 0x80000000u) ? (b & 0x7fffffffu) : ~b;
    return __uint_as_float(b);
}
__device__ __forceinline__ void bsplit(float v, __nv_bfloat16& h, __nv_bfloat16& l) {
    h = __float2bfloat16(v);
    l = __float2bfloat16(v - __bfloat162float(h));
}
__device__ __forceinline__ uint32_t smem_u32(const void* p) {
    uint32_t a;
    asm("{ .reg .u64 t; cvta.to.shared.u64 t, %1; cvt.u32.u64 %0, t; }" : "=r"(a) : "l"(p));
    return a;
}
__device__ __forceinline__ void ldm_x4(uint32_t& r0, uint32_t& r1, uint32_t& r2, uint32_t& r3,
                                       uint32_t addr) {
    asm volatile("ldmatrix.sync.aligned.m8n8.x4.shared.b16 {%0,%1,%2,%3}, [%4];"
                 : "=r"(r0), "=r"(r1), "=r"(r2), "=r"(r3) : "r"(addr));
}
__device__ __forceinline__ void mma16816(float* c, const uint32_t* a, uint32_t b0, uint32_t b1) {
    asm volatile(
        "mma.sync.aligned.m16n8k16.row.col.f32.bf16.bf16.f32 "
        "{%0,%1,%2,%3}, {%4,%5,%6,%7}, {%8,%9}, {%0,%1,%2,%3};"
        : "+f"(c[0]), "+f"(c[1]), "+f"(c[2]), "+f"(c[3])
        : "r"(a[0]), "r"(a[1]), "r"(a[2]), "r"(a[3]), "r"(b0), "r"(b1));
}

// ---------------- tiny learners ----------------
__global__ void k_nodeL(const float* __restrict__ nf, const float* __restrict__ W,
                        const float* __restrict__ b) {
    int idx = blockIdx.x * blockDim.x + threadIdx.x;
    if (idx >= NNODE * 32) return;
    int i = idx >> 5, j = idx & 31;
    const float* r = nf + i * 32;
    float s = b[j];
#pragma unroll
    for (int k = 0; k < 32; k++) s += r[k] * W[k * 32 + j];
    g_x[i * XD + GATD + j] = s;
}

__global__ void k_edgeL(const float* __restrict__ ea, const float* __restrict__ W,
                        const float* __restrict__ b) {
    int idx = blockIdx.x * blockDim.x + threadIdx.x;
    if (idx >= NEDGE * 16) return;
    int e = idx >> 4, j = idx & 15;
    const float* r = ea + e * 16;
    float s = b[j];
#pragma unroll
    for (int k = 0; k < 16; k++) s += r[k] * W[k * 16 + j];
    g_ea[e * 16 + j] = s;
}

// ---------------- split / transpose prep kernels ----------------
__global__ void k_splitA1(const float* __restrict__ src) {
    int idx = blockIdx.x * blockDim.x + threadIdx.x;
    if (idx >= NNODE * GATD) return;
    bsplit(src[idx], g_A1h[idx], g_A1l[idx]);
}
__global__ void k_splitW1(const float* __restrict__ Wg) {
    int idx = blockIdx.x * blockDim.x + threadIdx.x;
    if (idx >= GATD * GATD) return;
    int n = idx / GATD, k = idx % GATD;
    bsplit(Wg[k * GATD + n], g_W1h[idx], g_W1l[idx]);
}
__global__ void k_splitX() {
    int idx = blockIdx.x * blockDim.x + threadIdx.x;
    if (idx >= NNODE * XDP) return;
    int i = idx / XDP, k = idx % XDP;
    float v = (k < XD) ? g_x[i * XD + k] : 0.f;
    bsplit(v, g_Xh[idx], g_Xl[idx]);
}
__global__ void k_splitW2(const float* __restrict__ Wn, const float* __restrict__ Ws) {
    int idx = blockIdx.x * blockDim.x + threadIdx.x;
    if (idx >= PD * XDP) return;
    int n = idx / XDP, k = idx % XDP;
    float v = 0.f;
    if (k < XD) {
        if (n < 128)      v = Wn[k * 128 + n];
        else if (n < 256) v = Wn[(800 + k) * 128 + (n - 128)];
        else              v = Ws[k * 128 + (n - 256)];
    }
    bsplit(v, g_W2h[idx], g_W2l[idx]);
}

// ---------------- warp-MMA bf16-split GEMM ----------------
// C[M,CN] = (Ah+Al) @ (Bh+Bl)^T, A:[M,KPAD] K-major, B:[CN,KPAD] K-major.
// Block tile 128x128, 8 warps (2x4), warp tile 64x32, K chunk 32.
// smem row stride 40 bf16 (80B) -> conflict-free ldmatrix phases.
#define ASTRIDE 40

template <int CN, int KPAD, int NCH>
__device__ __forceinline__ void mma_gemm_body(const __nv_bfloat16* __restrict__ Ah,
                                              const __nv_bfloat16* __restrict__ Al,
                                              const __nv_bfloat16* __restrict__ Bh,
                                              const __nv_bfloat16* __restrict__ Bl,
                                              float* __restrict__ C) {
    __shared__ __nv_bfloat16 sAh[128 * ASTRIDE];
    __shared__ __nv_bfloat16 sAl[128 * ASTRIDE];
    __shared__ __nv_bfloat16 sBh[128 * ASTRIDE];
    __shared__ __nv_bfloat16 sBl[128 * ASTRIDE];

    const int t = threadIdx.x;
    const int lane = t & 31;
    const int wid = t >> 5;
    const int wm = wid >> 2;          // 0..1
    const int wn = wid & 3;           // 0..3
    const int m0 = wm * 64;
    const int n0 = wn * 32;
    const int bm = blockIdx.y * 128;
    const int bn = blockIdx.x * 128;

    const uint32_t baseAh = smem_u32(sAh), baseAl = smem_u32(sAl);
    const uint32_t baseBh = smem_u32(sBh), baseBl = smem_u32(sBl);

    // ldmatrix per-lane offsets (bytes)
    const uint32_t aoff = (uint32_t)(((lane & 15) * ASTRIDE + (lane >> 4) * 8) * 2);
    const uint32_t boff = (uint32_t)((((lane & 7) + ((lane >> 4) << 3)) * ASTRIDE +
                                     (((lane >> 3) & 1) << 3)) * 2);

    float acc[4][4][4];
#pragma unroll
    for (int i = 0; i < 4; i++)
#pragma unroll
        for (int j = 0; j < 4; j++)
#pragma unroll
            for (int q = 0; q < 4; q++) acc[i][j][q] = 0.f;

    // copy indices: 512 vec8 slots per tile, 2 per thread
    const int r0c = (t * 2) >> 3;          // rows step: idx = it*256+t -> r = idx>>2
    (void)r0c;

    for (int c = 0; c < NCH; c++) {
        const int c0 = c * 32;
        __syncthreads();
#pragma unroll
        for (int it = 0; it < 2; it++) {
            int idx = it * 256 + t;
            int r = idx >> 2, j = idx & 3;
            size_t ga = (size_t)(bm + r) * KPAD + c0 + j * 8;
            size_t gb = (size_t)(bn + r) * KPAD + c0 + j * 8;
            int so = r * ASTRIDE + j * 8;
            *(uint4*)&sAh[so] = *(const uint4*)&Ah[ga];
            *(uint4*)&sAl[so] = *(const uint4*)&Al[ga];
            *(uint4*)&sBh[so] = *(const uint4*)&Bh[gb];
            *(uint4*)&sBl[so] = *(const uint4*)&Bl[gb];
        }
        __syncthreads();

#pragma unroll
        for (int ks = 0; ks < 2; ks++) {
            const uint32_t kb = (uint32_t)(ks * 16 * 2);
            // B fragments for 4 n-tiles (two ldmatrix.x4 per h/l)
            uint32_t bh[2][4], bl[2][4];
#pragma unroll
            for (int p = 0; p < 2; p++) {
                uint32_t off = boff + (uint32_t)((n0 + p * 16) * ASTRIDE * 2) + kb;
                ldm_x4(bh[p][0], bh[p][1], bh[p][2], bh[p][3], baseBh + off);
                ldm_x4(bl[p][0], bl[p][1], bl[p][2], bl[p][3], baseBl + off);
            }
#pragma unroll
            for (int tm = 0; tm < 4; tm++) {
                uint32_t off = aoff + (uint32_t)((m0 + tm * 16) * ASTRIDE * 2) + kb;
                uint32_t ah[4], al[4];
                ldm_x4(ah[0], ah[1], ah[2], ah[3], baseAh + off);
                ldm_x4(al[0], al[1], al[2], al[3], baseAl + off);
#pragma unroll
                for (int tn = 0; tn < 4; tn++) {
                    int p = tn >> 1, q = tn & 1;
                    uint32_t B0h = bh[p][q * 2], B1h = bh[p][q * 2 + 1];
                    uint32_t B0l = bl[p][q * 2], B1l = bl[p][q * 2 + 1];
                    mma16816(acc[tm][tn], ah, B0h, B1h);
                    mma16816(acc[tm][tn], ah, B0l, B1l);
                    mma16816(acc[tm][tn], al, B0h, B1h);
                }
            }
        }
    }

    // epilogue
    const int rit = lane >> 2;
    const int cq = (lane & 3) * 2;
#pragma unroll
    for (int tm = 0; tm < 4; tm++)
#pragma unroll
        for (int tn = 0; tn < 4; tn++) {
            size_t row = (size_t)(bm + m0 + tm * 16 + rit);
            int col = bn + n0 + tn * 8 + cq;
            *(float2*)&C[row * CN + col] = make_float2(acc[tm][tn][0], acc[tm][tn][1]);
            *(float2*)&C[(row + 8) * CN + col] = make_float2(acc[tm][tn][2], acc[tm][tn][3]);
        }
}

__global__ void __launch_bounds__(256) k_gemm1() {
    mma_gemm_body<GATD, GATD, 24>(g_A1h, g_A1l, g_W1h, g_W1l, g_h);
}
__global__ void __launch_bounds__(256) k_gemm2() {
    mma_gemm_body<PD, XDP, 26>(g_Xh, g_Xl, g_W2h, g_W2l, g_P);
}

// ---------------- attention scalars ----------------
__global__ void k_att(const float* __restrict__ att_src, const float* __restrict__ att_dst) {
    int warp = (blockIdx.x * blockDim.x + threadIdx.x) >> 5;
    int lane = threadIdx.x & 31;
    if (warp >= NNODE) return;
    const float* hr = g_h + (size_t)warp * GATD;
    float s1 = 0.f, s2 = 0.f;
    for (int j = lane; j < GATD; j += 32) {
        float v = hr[j];
        s1 += v * att_src[j];
        s2 += v * att_dst[j];
    }
#pragma unroll
    for (int off = 16; off > 0; off >>= 1) {
        s1 += __shfl_down_sync(0xffffffffu, s1, off);
        s2 += __shfl_down_sync(0xffffffffu, s2, off);
    }
    if (lane == 0) { g_asrc[warp] = s1; g_adst[warp] = s2; }
}

__global__ void k_init_node() {
    int i = blockIdx.x * blockDim.x + threadIdx.x;
    if (i >= NNODE) return;
    float al = lrelu(g_asrc[i] + g_adst[i]);   // self-loop alpha
    g_amax[i] = f2o(al);
    g_deg[i] = 0;
}

__global__ void k_edge_alpha(const int* __restrict__ ei) {
    int e = blockIdx.x * blockDim.x + threadIdx.x;
    if (e >= NEDGE) return;
    int s = ei[e], d = ei[NEDGE + e];
    float al = lrelu(g_asrc[s] + g_adst[d]);
    g_alphaE[e] = al;
    atomicMax(&g_amax[d], f2o(al));
    atomicAdd(&g_deg[d], 1);
}

// exclusive scan of deg -> rowstart (and pos copy); one block
__global__ void k_scan() {
    __shared__ int sh[1024];
    __shared__ int s_carry;
    int tid = threadIdx.x;
    if (tid == 0) s_carry = 0;
    __syncthreads();
    for (int base = 0; base < NNODE; base += 1024) {
        int i = base + tid;
        int v = (i < NNODE) ? g_deg[i] : 0;
        sh[tid] = v;
        __syncthreads();
        for (int off = 1; off < 1024; off <<= 1) {
            int t = (tid >= off) ? sh[tid - off] : 0;
            __syncthreads();
            sh[tid] += t;
            __syncthreads();
        }
        int incl = sh[tid];
        int carry = s_carry;
        if (i < NNODE) {
            int excl = carry + incl - v;
            g_rowstart[i] = excl;
            g_pos[i] = excl;
        }
        __syncthreads();
        if (tid == 1023) s_carry = carry + incl;
        __syncthreads();
    }
}

__global__ void k_csr_fill(const int* __restrict__ ei) {
    int e = blockIdx.x * blockDim.x + threadIdx.x;
    if (e >= NEDGE) return;
    int s = ei[e], d = ei[NEDGE + e];
    int p = atomicAdd(&g_pos[d], 1);
    g_csr_src[p] = s;
    g_csr_eid[p] = e;
}

__global__ void k_denom_init() {
    int i = blockIdx.x * blockDim.x + threadIdx.x;
    if (i >= NNODE) return;
    float al = lrelu(g_asrc[i] + g_adst[i]);
    g_denom[i] = expf(al - o2f(g_amax[i]));
}

__global__ void k_edge_exp2(const int* __restrict__ ei) {
    int e = blockIdx.x * blockDim.x + threadIdx.x;
    if (e >= NEDGE) return;
    int d = ei[NEDGE + e];
    float ex = expf(g_alphaE[e] - o2f(g_amax[d]));
    g_exE[e] = ex;
    atomicAdd(&g_denom[d], ex);
}

// ---------------- GAT gather-aggregation: warp per node ----------------
__global__ void k_gat_aggr(const float* __restrict__ b_gat) {
    int warp = (blockIdx.x * blockDim.x + threadIdx.x) >> 5;
    int lane = threadIdx.x & 31;
    if (warp >= NNODE) return;
    int i = warp;
    float amaxv = o2f(g_amax[i]);
    float als = lrelu(g_asrc[i] + g_adst[i]);
    float inv_den = 1.0f / g_denom[i];
    float cs = expf(als - amaxv) * inv_den;

    const float4* hrow = (const float4*)(g_h + (size_t)i * GATD);
    const float4* bg = (const float4*)b_gat;
    float4 acc[6];
#pragma unroll
    for (int t = 0; t < 6; t++) {
        float4 hv = hrow[lane + 32 * t];
        float4 bv = bg[lane + 32 * t];
        acc[t].x = cs * hv.x + bv.x;
        acc[t].y = cs * hv.y + bv.y;
        acc[t].z = cs * hv.z + bv.z;
        acc[t].w = cs * hv.w + bv.w;
    }
    int rs = g_rowstart[i], d = g_deg[i];
    for (int k = 0; k < d; k++) {
        int s = g_csr_src[rs + k];
        float coef = g_exE[g_csr_eid[rs + k]] * inv_den;
        const float4* hs = (const float4*)(g_h + (size_t)s * GATD);
#pragma unroll
        for (int t = 0; t < 6; t++) {
            float4 hv = __ldg(&hs[lane + 32 * t]);
            acc[t].x += coef * hv.x;
            acc[t].y += coef * hv.y;
            acc[t].z += coef * hv.z;
            acc[t].w += coef * hv.w;
        }
    }
    float4* xrow = (float4*)(g_x + (size_t)i * XD);
#pragma unroll
    for (int t = 0; t < 6; t++) xrow[lane + 32 * t] = acc[t];
}

// ---------------- EW[e] = ea[e] @ W_nbr[1600:1616]  (2 edges / 256-thr block) ----------------
__global__ void k_ew(const float* __restrict__ W_nbr) {
    __shared__ float We[16 * 128];
    for (int t = threadIdx.x; t < 2048; t += 256) We[t] = W_nbr[1600 * 128 + t];
    __syncthreads();
    int e = blockIdx.x * 2 + (threadIdx.x >> 7);
    int d = threadIdx.x & 127;
    const float* ear = g_ea + e * 16;
    float s = 0.f;
#pragma unroll
    for (int k = 0; k < 16; k++) s += ear[k] * We[k * 128 + d];
    g_EW[e * 128 + d] = s;
}

// ---------------- final aggregation: warp per node, lane = 4 output dims ----------------
__global__ void k_meta(float* __restrict__ out, const float* __restrict__ b_nbr,
                       const float* __restrict__ b_self) {
    int warp = (blockIdx.x * blockDim.x + threadIdx.x) >> 5;
    int lane = threadIdx.x & 31;
    if (warp >= NNODE) return;
    int i = warp;
    const float4* Pr = (const float4*)(g_P + (size_t)i * PD);
    float4 p1 = Pr[lane];        // dst-part
    float4 xs = Pr[64 + lane];   // self-part
    float4 bn = ((const float4*)b_nbr)[lane];
    float4 bs = ((const float4*)b_self)[lane];
    float degf = (float)g_deg[i];
    float4 acc;
    acc.x = xs.x + bs.x + degf * (p1.x + bn.x);
    acc.y = xs.y + bs.y + degf * (p1.y + bn.y);
    acc.z = xs.z + bs.z + degf * (p1.z + bn.z);
    acc.w = xs.w + bs.w + degf * (p1.w + bn.w);
    int rs = g_rowstart[i], d = g_deg[i];
    for (int k = 0; k < d; k++) {
        int s = g_csr_src[rs + k];
        int e = g_csr_eid[rs + k];
        float4 p2 = __ldg(&((const float4*)(g_P + (size_t)s * PD))[32 + lane]);
        float4 ew = __ldg(&((const float4*)(g_EW + (size_t)e * MD))[lane]);
        acc.x += p2.x + ew.x;
        acc.y += p2.y + ew.y;
        acc.z += p2.z + ew.z;
        acc.w += p2.w + ew.w;
    }
    ((float4*)(out + (size_t)i * MD))[lane] = acc;
}

// ---------------- launch ----------------
extern "C" void kernel_launch(void* const* d_in, const int* in_sizes, int n_in,
                              void* d_out, int out_size) {
    const float* node_feature    = (const float*)d_in[0];
    const float* edge_attr       = (const float*)d_in[1];
    const float* message_feature = (const float*)d_in[2];
    const int*   edge_index      = (const int*)d_in[3];
    const float* W_node = (const float*)d_in[4];
    const float* b_node = (const float*)d_in[5];
    const float* W_edge = (const float*)d_in[6];
    const float* b_edge = (const float*)d_in[7];
    const float* W_gat  = (const float*)d_in[8];
    const float* att_src = (const float*)d_in[9];
    const float* att_dst = (const float*)d_in[10];
    const float* b_gat  = (const float*)d_in[11];
    const float* W_nbr  = (const float*)d_in[12];
    const float* b_nbr  = (const float*)d_in[13];
    const float* W_self = (const float*)d_in[14];
    const float* b_self = (const float*)d_in[15];
    float* out = (float*)d_out;

    // learners + GEMM1 prep
    k_nodeL<<<(NNODE * 32 + 255) / 256, 256>>>(node_feature, W_node, b_node);
    k_edgeL<<<(NEDGE * 16 + 255) / 256, 256>>>(edge_attr, W_edge, b_edge);
    k_splitA1<<<(NNODE * GATD + 255) / 256, 256>>>(message_feature);
    k_splitW1<<<(GATD * GATD + 255) / 256, 256>>>(W_gat);

    // h = mf @ W_gat  (bf16 3-term split, mma.sync tensor cores)
    k_gemm1<<<dim3(GATD / 128, NNODE / 128), 256>>>();

    // attention scalars + softmax structure
    k_att<<<(NNODE * 32 + 255) / 256, 256>>>(att_src, att_dst);
    k_init_node<<<(NNODE + 255) / 256, 256>>>();
    k_edge_alpha<<<(NEDGE + 255) / 256, 256>>>(edge_index);
    k_scan<<<1, 1024>>>();
    k_csr_fill<<<(NEDGE + 255) / 256, 256>>>(edge_index);
    k_denom_init<<<(NNODE + 255) / 256, 256>>>();
    k_edge_exp2<<<(NEDGE + 255) / 256, 256>>>(edge_index);

    // GAT aggregation -> x[:, 0:768]
    k_gat_aggr<<<(NNODE * 32 + 255) / 256, 256>>>(b_gat);

    // GEMM2 prep + P = x @ Wcat  (bf16 3-term split)
    k_splitX<<<(NNODE * XDP + 255) / 256, 256>>>();
    k_splitW2<<<(PD * XDP + 255) / 256, 256>>>(W_nbr, W_self);
    k_gemm2<<<dim3(PD / 128, NNODE / 128), 256>>>();

    k_ew<<<NEDGE / 2, 256>>>(W_nbr);

    // final per-node aggregation -> out
    k_meta<<<(NNODE * 32 + 255) / 256, 256>>>(out, b_nbr, b_self);
}

// round 4
// speedup vs baseline: 2.1417x; 1.4042x over previous
#include <cuda_runtime.h>
#include <cuda_bf16.h>
#include <cstdint>

// ---------------- problem constants ----------------
#define NNODE 16000
#define NEDGE 128000
#define GATD 768          // GAT dim
#define XD 800            // meta-in dim (768 gat + 32 node)
#define XDP 832           // padded K for GEMM2 (26 x 32)
#define MD 128            // meta out dim
#define PD 384            // P1(dst part) | P2(src part) | Xself

// ---------------- device scratch (no allocs allowed) ----------------
__device__ float    g_h[NNODE * GATD];       // 49 MB
__device__ float    g_P[NNODE * PD];         // 24.6 MB
__device__ float    g_ea[NEDGE * 16];        // 8.2 MB
__device__ float    g_asrc[NNODE];
__device__ float    g_adst[NNODE];
__device__ unsigned g_amax[NNODE];           // ordered-float bits
__device__ float    g_denom[NNODE];
__device__ float    g_alphaE[NEDGE];
__device__ float    g_exE[NEDGE];
__device__ int      g_deg[NNODE];
__device__ int      g_rowstart[NNODE];
__device__ int      g_pos[NNODE];
__device__ int      g_csr_src[NEDGE];
__device__ int      g_csr_eid[NEDGE];
// bf16 split operands for tensor-core GEMMs
__device__ __nv_bfloat16 g_A1h[NNODE * GATD];
__device__ __nv_bfloat16 g_A1l[NNODE * GATD];
__device__ __nv_bfloat16 g_Xh[NNODE * XDP];
__device__ __nv_bfloat16 g_Xl[NNODE * XDP];
__device__ __nv_bfloat16 g_W1h[GATD * GATD];   // W_gat^T  [n,k]
__device__ __nv_bfloat16 g_W1l[GATD * GATD];
__device__ __nv_bfloat16 g_W2h[PD * XDP];      // Wcat^T   [n,k]
__device__ __nv_bfloat16 g_W2l[PD * XDP];

// ---------------- helpers ----------------
__device__ __forceinline__ float lrelu(float x) { return x >= 0.f ? x : 0.2f * x; }
__device__ __forceinline__ unsigned f2o(float f) {
    unsigned b = __float_as_uint(f);
    return (b & 0x80000000u) ? ~b : (b | 0x80000000u);
}
__device__ __forceinline__ float o2f(unsigned b) {
    b = (b & 0x80000000u) ? (b & 0x7fffffffu) : ~b;
    return __uint_as_float(b);
}
__device__ __forceinline__ void bsplit(float v, __nv_bfloat16& h, __nv_bfloat16& l) {
    h = __float2bfloat16(v);
    l = __float2bfloat16(v - __bfloat162float(h));
}
__device__ __forceinline__ uint32_t smem_u32(const void* p) {
    uint32_t a;
    asm("{ .reg .u64 t; cvta.to.shared.u64 t, %1; cvt.u32.u64 %0, t; }" : "=r"(a) : "l"(p));
    return a;
}
__device__ __forceinline__ void ldm_x4(uint32_t& r0, uint32_t& r1, uint32_t& r2, uint32_t& r3,
                                       uint32_t addr) {
    asm volatile("ldmatrix.sync.aligned.m8n8.x4.shared.b16 {%0,%1,%2,%3}, [%4];"
                 : "=r"(r0), "=r"(r1), "=r"(r2), "=r"(r3) : "r"(addr));
}
__device__ __forceinline__ void mma16816(float* c, const uint32_t* a, uint32_t b0, uint32_t b1) {
    asm volatile(
        "mma.sync.aligned.m16n8k16.row.col.f32.bf16.bf16.f32 "
        "{%0,%1,%2,%3}, {%4,%5,%6,%7}, {%8,%9}, {%0,%1,%2,%3};"
        : "+f"(c[0]), "+f"(c[1]), "+f"(c[2]), "+f"(c[3])
        : "r"(a[0]), "r"(a[1]), "r"(a[2]), "r"(a[3]), "r"(b0), "r"(b1));
}
__device__ __forceinline__ void cp16(uint32_t dst, const void* src) {
    asm volatile("cp.async.cg.shared.global [%0], [%1], 16;" :: "r"(dst), "l"(src));
}
#define CP_COMMIT() asm volatile("cp.async.commit_group;" ::: "memory")
#define CP_WAIT1()  asm volatile("cp.async.wait_group 1;" ::: "memory")
#define CP_WAIT0()  asm volatile("cp.async.wait_group 0;" ::: "memory")

// ---------------- tiny learners ----------------
__global__ void k_nodeL(const float* __restrict__ nf, const float* __restrict__ W,
                        const float* __restrict__ b) {
    int idx = blockIdx.x * blockDim.x + threadIdx.x;
    if (idx >= NNODE * 32) return;
    int i = idx >> 5, j = idx & 31;
    const float* r = nf + i * 32;
    float s = b[j];
#pragma unroll
    for (int k = 0; k < 32; k++) s += r[k] * W[k * 32 + j];
    __nv_bfloat16 hh, ll;
    bsplit(s, hh, ll);
    size_t base = (size_t)i * XDP;
    g_Xh[base + 768 + j] = hh;
    g_Xl[base + 768 + j] = ll;
    // zero pad cols 800:832 (one pad element per thread)
    g_Xh[base + 800 + j] = __float2bfloat16(0.f);
    g_Xl[base + 800 + j] = __float2bfloat16(0.f);
}

__global__ void k_edgeL(const float* __restrict__ ea, const float* __restrict__ W,
                        const float* __restrict__ b) {
    int idx = blockIdx.x * blockDim.x + threadIdx.x;
    if (idx >= NEDGE * 16) return;
    int e = idx >> 4, j = idx & 15;
    const float* r = ea + e * 16;
    float s = b[j];
#pragma unroll
    for (int k = 0; k < 16; k++) s += r[k] * W[k * 16 + j];
    g_ea[e * 16 + j] = s;
}

// ---------------- split / transpose prep kernels ----------------
__global__ void k_splitA1(const float* __restrict__ src) {
    int idx = blockIdx.x * blockDim.x + threadIdx.x;
    if (idx >= NNODE * GATD) return;
    bsplit(src[idx], g_A1h[idx], g_A1l[idx]);
}
__global__ void k_splitW1(const float* __restrict__ Wg) {
    int idx = blockIdx.x * blockDim.x + threadIdx.x;
    if (idx >= GATD * GATD) return;
    int n = idx / GATD, k = idx % GATD;
    bsplit(Wg[k * GATD + n], g_W1h[idx], g_W1l[idx]);
}
__global__ void k_splitW2(const float* __restrict__ Wn, const float* __restrict__ Ws) {
    int idx = blockIdx.x * blockDim.x + threadIdx.x;
    if (idx >= PD * XDP) return;
    int n = idx / XDP, k = idx % XDP;
    float v = 0.f;
    if (k < XD) {
        if (n < 128)      v = Wn[k * 128 + n];
        else if (n < 256) v = Wn[(800 + k) * 128 + (n - 128)];
        else              v = Ws[k * 128 + (n - 256)];
    }
    bsplit(v, g_W2h[idx], g_W2l[idx]);
}

// ---------------- warp-MMA bf16-split GEMM (cp.async double-buffered) ----------------
// C[M,CN] = (Ah+Al) @ (Bh+Bl)^T, A:[M,KPAD] K-major, B:[CN,KPAD] K-major.
// Block tile 128x128, 8 warps (2x4), warp tile 64x32, K chunk 32.
// smem row stride 40 bf16 (80B) -> conflict-free ldmatrix phases.
#define ASTRIDE 40
#define TILE_BYTES 10240                  // 128*40*2
#define STAGE_BYTES (4 * TILE_BYTES)      // Ah|Al|Bh|Bl

template <int CN, int KPAD, int NCH>
__device__ __forceinline__ void mma_gemm_body(const __nv_bfloat16* __restrict__ Ah,
                                              const __nv_bfloat16* __restrict__ Al,
                                              const __nv_bfloat16* __restrict__ Bh,
                                              const __nv_bfloat16* __restrict__ Bl,
                                              float* __restrict__ C) {
    extern __shared__ char smem[];
    const uint32_t sb = smem_u32(smem);

    const int t = threadIdx.x;
    const int lane = t & 31;
    const int wid = t >> 5;
    const int m0 = (wid >> 2) * 64;
    const int n0 = (wid & 3) * 32;
    const int bm = blockIdx.y * 128;
    const int bn = blockIdx.x * 128;

    // ldmatrix per-lane offsets (bytes)
    const uint32_t aoff = (uint32_t)(((lane & 15) * ASTRIDE + (lane >> 4) * 8) * 2);
    const uint32_t boff = (uint32_t)((((lane & 7) + ((lane >> 4) << 3)) * ASTRIDE +
                                     (((lane >> 3) & 1) << 3)) * 2);

    float acc[4][4][4];
#pragma unroll
    for (int i = 0; i < 4; i++)
#pragma unroll
        for (int j = 0; j < 4; j++)
#pragma unroll
            for (int q = 0; q < 4; q++) acc[i][j][q] = 0.f;

    auto issue_chunk = [&](int c, int s) {
        const int c0 = c * 32;
        const uint32_t dst = sb + (uint32_t)s * STAGE_BYTES;
#pragma unroll
        for (int it = 0; it < 2; it++) {
            int idx = it * 256 + t;
            int r = idx >> 2, j = idx & 3;
            size_t ga = (size_t)(bm + r) * KPAD + c0 + j * 8;
            size_t gb = (size_t)(bn + r) * KPAD + c0 + j * 8;
            uint32_t doff = (uint32_t)((r * ASTRIDE + j * 8) * 2);
            cp16(dst + doff, Ah + ga);
            cp16(dst + TILE_BYTES + doff, Al + ga);
            cp16(dst + 2 * TILE_BYTES + doff, Bh + gb);
            cp16(dst + 3 * TILE_BYTES + doff, Bl + gb);
        }
    };

    issue_chunk(0, 0);
    CP_COMMIT();

    for (int c = 0; c < NCH; c++) {
        const int s = c & 1;
        if (c + 1 < NCH) {
            issue_chunk(c + 1, s ^ 1);
            CP_COMMIT();
            CP_WAIT1();
        } else {
            CP_WAIT0();
        }
        __syncthreads();

        const uint32_t baseAh = sb + (uint32_t)s * STAGE_BYTES;
        const uint32_t baseAl = baseAh + TILE_BYTES;
        const uint32_t baseBh = baseAh + 2 * TILE_BYTES;
        const uint32_t baseBl = baseAh + 3 * TILE_BYTES;

#pragma unroll
        for (int ks = 0; ks < 2; ks++) {
            const uint32_t kb = (uint32_t)(ks * 16 * 2);
            uint32_t bh[2][4], bl[2][4];
#pragma unroll
            for (int p = 0; p < 2; p++) {
                uint32_t off = boff + (uint32_t)((n0 + p * 16) * ASTRIDE * 2) + kb;
                ldm_x4(bh[p][0], bh[p][1], bh[p][2], bh[p][3], baseBh + off);
                ldm_x4(bl[p][0], bl[p][1], bl[p][2], bl[p][3], baseBl + off);
            }
#pragma unroll
            for (int tm = 0; tm < 4; tm++) {
                uint32_t off = aoff + (uint32_t)((m0 + tm * 16) * ASTRIDE * 2) + kb;
                uint32_t ah[4], al[4];
                ldm_x4(ah[0], ah[1], ah[2], ah[3], baseAh + off);
                ldm_x4(al[0], al[1], al[2], al[3], baseAl + off);
#pragma unroll
                for (int tn = 0; tn < 4; tn++) {
                    int p = tn >> 1, q = tn & 1;
                    uint32_t B0h = bh[p][q * 2], B1h = bh[p][q * 2 + 1];
                    uint32_t B0l = bl[p][q * 2], B1l = bl[p][q * 2 + 1];
                    mma16816(acc[tm][tn], ah, B0h, B1h);
                    mma16816(acc[tm][tn], ah, B0l, B1l);
                    mma16816(acc[tm][tn], al, B0h, B1h);
                }
            }
        }
        __syncthreads();
    }

    // epilogue
    const int rit = lane >> 2;
    const int cq = (lane & 3) * 2;
#pragma unroll
    for (int tm = 0; tm < 4; tm++)
#pragma unroll
        for (int tn = 0; tn < 4; tn++) {
            size_t row = (size_t)(bm + m0 + tm * 16 + rit);
            int col = bn + n0 + tn * 8 + cq;
            *(float2*)&C[row * CN + col] = make_float2(acc[tm][tn][0], acc[tm][tn][1]);
            *(float2*)&C[(row + 8) * CN + col] = make_float2(acc[tm][tn][2], acc[tm][tn][3]);
        }
}

__global__ void __launch_bounds__(256) k_gemm1() {
    mma_gemm_body<GATD, GATD, 24>(g_A1h, g_A1l, g_W1h, g_W1l, g_h);
}
__global__ void __launch_bounds__(256) k_gemm2() {
    mma_gemm_body<PD, XDP, 26>(g_Xh, g_Xl, g_W2h, g_W2l, g_P);
}

// ---------------- attention scalars ----------------
__global__ void k_att(const float* __restrict__ att_src, const float* __restrict__ att_dst) {
    int warp = (blockIdx.x * blockDim.x + threadIdx.x) >> 5;
    int lane = threadIdx.x & 31;
    if (warp >= NNODE) return;
    const float* hr = g_h + (size_t)warp * GATD;
    float s1 = 0.f, s2 = 0.f;
    for (int j = lane; j < GATD; j += 32) {
        float v = hr[j];
        s1 += v * att_src[j];
        s2 += v * att_dst[j];
    }
#pragma unroll
    for (int off = 16; off > 0; off >>= 1) {
        s1 += __shfl_down_sync(0xffffffffu, s1, off);
        s2 += __shfl_down_sync(0xffffffffu, s2, off);
    }
    if (lane == 0) { g_asrc[warp] = s1; g_adst[warp] = s2; }
}

__global__ void k_init_node() {
    int i = blockIdx.x * blockDim.x + threadIdx.x;
    if (i >= NNODE) return;
    float al = lrelu(g_asrc[i] + g_adst[i]);   // self-loop alpha
    g_amax[i] = f2o(al);
    g_deg[i] = 0;
}

__global__ void k_edge_alpha(const int* __restrict__ ei) {
    int e = blockIdx.x * blockDim.x + threadIdx.x;
    if (e >= NEDGE) return;
    int s = ei[e], d = ei[NEDGE + e];
    float al = lrelu(g_asrc[s] + g_adst[d]);
    g_alphaE[e] = al;
    atomicMax(&g_amax[d], f2o(al));
    atomicAdd(&g_deg[d], 1);
}

// exclusive scan of deg -> rowstart (and pos copy); one block
__global__ void k_scan() {
    __shared__ int sh[1024];
    __shared__ int s_carry;
    int tid = threadIdx.x;
    if (tid == 0) s_carry = 0;
    __syncthreads();
    for (int base = 0; base < NNODE; base += 1024) {
        int i = base + tid;
        int v = (i < NNODE) ? g_deg[i] : 0;
        sh[tid] = v;
        __syncthreads();
        for (int off = 1; off < 1024; off <<= 1) {
            int t = (tid >= off) ? sh[tid - off] : 0;
            __syncthreads();
            sh[tid] += t;
            __syncthreads();
        }
        int incl = sh[tid];
        int carry = s_carry;
        if (i < NNODE) {
            int excl = carry + incl - v;
            g_rowstart[i] = excl;
            g_pos[i] = excl;
        }
        __syncthreads();
        if (tid == 1023) s_carry = carry + incl;
        __syncthreads();
    }
}

__global__ void k_csr_fill(const int* __restrict__ ei) {
    int e = blockIdx.x * blockDim.x + threadIdx.x;
    if (e >= NEDGE) return;
    int s = ei[e], d = ei[NEDGE + e];
    int p = atomicAdd(&g_pos[d], 1);
    g_csr_src[p] = s;
    g_csr_eid[p] = e;
}

__global__ void k_denom_init() {
    int i = blockIdx.x * blockDim.x + threadIdx.x;
    if (i >= NNODE) return;
    float al = lrelu(g_asrc[i] + g_adst[i]);
    g_denom[i] = expf(al - o2f(g_amax[i]));
}

__global__ void k_edge_exp2(const int* __restrict__ ei) {
    int e = blockIdx.x * blockDim.x + threadIdx.x;
    if (e >= NEDGE) return;
    int d = ei[NEDGE + e];
    float ex = expf(g_alphaE[e] - o2f(g_amax[d]));
    g_exE[e] = ex;
    atomicAdd(&g_denom[d], ex);
}

// ---------------- GAT gather-aggregation: warp per node, writes bf16 split x ----------------
__global__ void k_gat_aggr(const float* __restrict__ b_gat) {
    int warp = (blockIdx.x * blockDim.x + threadIdx.x) >> 5;
    int lane = threadIdx.x & 31;
    if (warp >= NNODE) return;
    int i = warp;
    float amaxv = o2f(g_amax[i]);
    float als = lrelu(g_asrc[i] + g_adst[i]);
    float inv_den = 1.0f / g_denom[i];
    float cs = expf(als - amaxv) * inv_den;

    const float4* hrow = (const float4*)(g_h + (size_t)i * GATD);
    const float4* bg = (const float4*)b_gat;
    float4 acc[6];
#pragma unroll
    for (int t = 0; t < 6; t++) {
        float4 hv = hrow[lane + 32 * t];
        float4 bv = bg[lane + 32 * t];
        acc[t].x = cs * hv.x + bv.x;
        acc[t].y = cs * hv.y + bv.y;
        acc[t].z = cs * hv.z + bv.z;
        acc[t].w = cs * hv.w + bv.w;
    }
    int rs = g_rowstart[i], d = g_deg[i];
    for (int k = 0; k < d; k++) {
        int s = g_csr_src[rs + k];
        float coef = g_exE[g_csr_eid[rs + k]] * inv_den;
        const float4* hs = (const float4*)(g_h + (size_t)s * GATD);
#pragma unroll
        for (int t = 0; t < 6; t++) {
            float4 hv = __ldg(&hs[lane + 32 * t]);
            acc[t].x += coef * hv.x;
            acc[t].y += coef * hv.y;
            acc[t].z += coef * hv.z;
            acc[t].w += coef * hv.w;
        }
    }
    // write bf16 hi/lo split directly (cols 4*(lane+32t) .. +3)
    size_t base = (size_t)i * XDP;
#pragma unroll
    for (int t = 0; t < 6; t++) {
        int col = 4 * (lane + 32 * t);
        __nv_bfloat16 h0, h1, h2, h3, l0, l1, l2, l3;
        bsplit(acc[t].x, h0, l0);
        bsplit(acc[t].y, h1, l1);
        bsplit(acc[t].z, h2, l2);
        bsplit(acc[t].w, h3, l3);
        __nv_bfloat162* ph = (__nv_bfloat162*)(g_Xh + base + col);
        __nv_bfloat162* pl = (__nv_bfloat162*)(g_Xl + base + col);
        ph[0] = __nv_bfloat162(h0, h1);
        ph[1] = __nv_bfloat162(h2, h3);
        pl[0] = __nv_bfloat162(l0, l1);
        pl[1] = __nv_bfloat162(l2, l3);
    }
}

// ---------------- final aggregation (fused ea@We): warp per node ----------------
__global__ void k_meta(float* __restrict__ out, const float* __restrict__ b_nbr,
                       const float* __restrict__ b_self, const float* __restrict__ W_nbr) {
    __shared__ float sWe[16 * 128];
    for (int t = threadIdx.x; t < 2048; t += blockDim.x)
        sWe[t] = W_nbr[1600 * 128 + t];
    __syncthreads();

    int warp = (blockIdx.x * blockDim.x + threadIdx.x) >> 5;
    int lane = threadIdx.x & 31;
    if (warp >= NNODE) return;
    int i = warp;
    const float4* Pr = (const float4*)(g_P + (size_t)i * PD);
    float4 p1 = Pr[lane];        // dst-part
    float4 xs = Pr[64 + lane];   // self-part
    float4 bn = ((const float4*)b_nbr)[lane];
    float4 bs = ((const float4*)b_self)[lane];
    float degf = (float)g_deg[i];
    float4 acc;
    acc.x = xs.x + bs.x + degf * (p1.x + bn.x);
    acc.y = xs.y + bs.y + degf * (p1.y + bn.y);
    acc.z = xs.z + bs.z + degf * (p1.z + bn.z);
    acc.w = xs.w + bs.w + degf * (p1.w + bn.w);

    float eas[16];
#pragma unroll
    for (int k = 0; k < 16; k++) eas[k] = 0.f;

    int rs = g_rowstart[i], d = g_deg[i];
    for (int k = 0; k < d; k++) {
        int s = g_csr_src[rs + k];
        int e = g_csr_eid[rs + k];
        float4 p2 = __ldg(&((const float4*)(g_P + (size_t)s * PD))[32 + lane]);
        acc.x += p2.x;
        acc.y += p2.y;
        acc.z += p2.z;
        acc.w += p2.w;
        const float4* ear = (const float4*)(g_ea + (size_t)e * 16);
        float4 e0 = __ldg(ear), e1 = __ldg(ear + 1), e2 = __ldg(ear + 2), e3 = __ldg(ear + 3);
        eas[0] += e0.x;  eas[1] += e0.y;  eas[2] += e0.z;  eas[3] += e0.w;
        eas[4] += e1.x;  eas[5] += e1.y;  eas[6] += e1.z;  eas[7] += e1.w;
        eas[8] += e2.x;  eas[9] += e2.y;  eas[10] += e2.z; eas[11] += e2.w;
        eas[12] += e3.x; eas[13] += e3.y; eas[14] += e3.z; eas[15] += e3.w;
    }

    // (sum of ea rows) @ We : lane handles 4 output cols
    int col = lane * 4;
#pragma unroll
    for (int kk = 0; kk < 16; kk++) {
        float4 wv = *(const float4*)&sWe[kk * 128 + col];
        float ev = eas[kk];
        acc.x += ev * wv.x;
        acc.y += ev * wv.y;
        acc.z += ev * wv.z;
        acc.w += ev * wv.w;
    }
    ((float4*)(out + (size_t)i * MD))[lane] = acc;
}

// ---------------- launch ----------------
extern "C" void kernel_launch(void* const* d_in, const int* in_sizes, int n_in,
                              void* d_out, int out_size) {
    const float* node_feature    = (const float*)d_in[0];
    const float* edge_attr       = (const float*)d_in[1];
    const float* message_feature = (const float*)d_in[2];
    const int*   edge_index      = (const int*)d_in[3];
    const float* W_node = (const float*)d_in[4];
    const float* b_node = (const float*)d_in[5];
    const float* W_edge = (const float*)d_in[6];
    const float* b_edge = (const float*)d_in[7];
    const float* W_gat  = (const float*)d_in[8];
    const float* att_src = (const float*)d_in[9];
    const float* att_dst = (const float*)d_in[10];
    const float* b_gat  = (const float*)d_in[11];
    const float* W_nbr  = (const float*)d_in[12];
    const float* b_nbr  = (const float*)d_in[13];
    const float* W_self = (const float*)d_in[14];
    const float* b_self = (const float*)d_in[15];
    float* out = (float*)d_out;

    const int GEMM_SMEM = 2 * STAGE_BYTES;   // 81920
    static int s_attr_done = 0;
    if (!s_attr_done) {
        cudaFuncSetAttribute(k_gemm1, cudaFuncAttributeMaxDynamicSharedMemorySize, GEMM_SMEM);
        cudaFuncSetAttribute(k_gemm2, cudaFuncAttributeMaxDynamicSharedMemorySize, GEMM_SMEM);
        s_attr_done = 1;
    }

    // learners + GEMM1 prep
    k_nodeL<<<(NNODE * 32 + 255) / 256, 256>>>(node_feature, W_node, b_node);
    k_edgeL<<<(NEDGE * 16 + 255) / 256, 256>>>(edge_attr, W_edge, b_edge);
    k_splitA1<<<(NNODE * GATD + 255) / 256, 256>>>(message_feature);
    k_splitW1<<<(GATD * GATD + 255) / 256, 256>>>(W_gat);

    // h = mf @ W_gat  (bf16 3-term split, mma.sync, cp.async pipelined)
    k_gemm1<<<dim3(GATD / 128, NNODE / 128), 256, GEMM_SMEM>>>();

    // attention scalars + softmax structure
    k_att<<<(NNODE * 32 + 255) / 256, 256>>>(att_src, att_dst);
    k_init_node<<<(NNODE + 255) / 256, 256>>>();
    k_edge_alpha<<<(NEDGE + 255) / 256, 256>>>(edge_index);
    k_scan<<<1, 1024>>>();
    k_csr_fill<<<(NEDGE + 255) / 256, 256>>>(edge_index);
    k_denom_init<<<(NNODE + 255) / 256, 256>>>();
    k_edge_exp2<<<(NEDGE + 255) / 256, 256>>>(edge_index);

    // GAT aggregation -> Xh/Xl cols 0:768 (bf16 split, direct)
    k_gat_aggr<<<(NNODE * 32 + 255) / 256, 256>>>(b_gat);

    // GEMM2 prep + P = x @ Wcat  (bf16 3-term split)
    k_splitW2<<<(PD * XDP + 255) / 256, 256>>>(W_nbr, W_self);
    k_gemm2<<<dim3(PD / 128, NNODE / 128), 256, GEMM_SMEM>>>();

    // final per-node aggregation (fused ea@We) -> out
    k_meta<<<(NNODE * 32 + 255) / 256, 256>>>(out, b_nbr, b_self, W_nbr);
}